// round 2
// baseline (speedup 1.0000x reference)
#include <cuda_runtime.h>
#include <cstdint>
#include <cstddef>

#define FULLMASK 0xFFFFFFFFu

namespace {
constexpr int HW      = 4096;   // 64*64
constexpr int KSEL    = 409;    // int(0.1 * 4096)
constexpr int NTHREAD = 256;
constexpr int NELEM   = 16;     // elements per thread
constexpr int NVEC    = 4;      // uint4 loads per thread
constexpr int NWARP   = 8;
}

struct SmemT {
    unsigned hist[NWARP * 256]; // warp-private histograms
    unsigned wsum[NWARP];
    unsigned wsum2[NWARP];
    unsigned sel_bin;
    unsigned sel_r;
    unsigned eqcnt;
    unsigned eqidx[64];
};

// One 8-bit (or 7-bit) radix-select level. key prefix (key >> gsh) must equal pv
// for an element to participate; bin = (key >> bsh) & bmask. Finds the bin b such
// that the r-th largest participating key lies in it, updates pv and r.
__device__ __forceinline__ void run_level(
    SmemT* sm, const unsigned* key,
    unsigned gsh, unsigned bsh, unsigned bmask, int nb,
    int tid, int lane, int wid, unsigned& pv, unsigned& r)
{
#pragma unroll
    for (int i = 0; i < (NWARP * 256) / NTHREAD; i++)
        sm->hist[tid + i * NTHREAD] = 0;
    __syncthreads();

#pragma unroll
    for (int e = 0; e < NELEM; e++) {
        unsigned k = key[e];
        bool pred = ((k >> gsh) == pv);
        unsigned bin = (k >> bsh) & bmask;
        unsigned act = __ballot_sync(FULLMASK, pred);
        if (pred) {
            unsigned m = __match_any_sync(act, bin);
            if (lane == __ffs(m) - 1)   // leader of each equal-bin group
                sm->hist[(wid << 8) + bin] += (unsigned)__popc(m);
        }
        __syncwarp();  // order leader RMWs across iterations (no atomics needed)
    }
    __syncthreads();

    // Descending cumulative scan over bins: thread t owns bin nb-1-t.
    unsigned s = 0;
    int b = nb - 1 - tid;
    if (b >= 0) {
#pragma unroll
        for (int w = 0; w < NWARP; w++) s += sm->hist[(w << 8) + b];
    }
    unsigned incl = s;
#pragma unroll
    for (int d = 1; d < 32; d <<= 1) {
        unsigned nn = __shfl_up_sync(FULLMASK, incl, d);
        if (lane >= d) incl += nn;
    }
    if (lane == 31) sm->wsum[wid] = incl;
    __syncthreads();
#pragma unroll
    for (int w = 0; w < NWARP - 1; w++)
        if (w < wid) incl += sm->wsum[w];
    // exactly one thread crosses rank r (s==0 threads cannot satisfy incl-s < r)
    if (incl >= r && (incl - s) < r) {
        sm->sel_bin = (unsigned)b;
        sm->sel_r = r - (incl - s);
    }
    __syncthreads();
    unsigned bits = (bmask == 0x7Fu) ? 7u : 8u;
    pv = (pv << bits) | sm->sel_bin;
    r = sm->sel_r;
    __syncthreads();
}

__global__ __launch_bounds__(NTHREAD, 4)
void topk_sparse_kernel(const float* __restrict__ x, float* __restrict__ y)
{
    __shared__ SmemT sm;
    const int tid  = threadIdx.x;
    const int lane = tid & 31;
    const int wid  = tid >> 5;
    const size_t rowbase = (size_t)blockIdx.x * (HW / 4);

    const uint4* xin  = reinterpret_cast<const uint4*>(x) + rowbase;
    uint4*       yout = reinterpret_cast<uint4*>(y) + rowbase;

    unsigned key[NELEM];
    unsigned signs = 0;
#pragma unroll
    for (int j = 0; j < NVEC; j++) {
        uint4 u = xin[tid + j * NTHREAD];
        key[4*j+0] = u.x & 0x7FFFFFFFu; signs |= (u.x >> 31) << (4*j+0);
        key[4*j+1] = u.y & 0x7FFFFFFFu; signs |= (u.y >> 31) << (4*j+1);
        key[4*j+2] = u.z & 0x7FFFFFFFu; signs |= (u.z >> 31) << (4*j+2);
        key[4*j+3] = u.w & 0x7FFFFFFFu; signs |= (u.w >> 31) << (4*j+3);
    }

    // ---- Fast exponent shortcut: count |x| >= 1.0 and |x| >= 2.0 ----
    unsigned c1 = 0, c2 = 0;
#pragma unroll
    for (int e = 0; e < NELEM; e++) {
        c1 += (key[e] >= (127u << 23)) ? 1u : 0u;
        c2 += (key[e] >= (128u << 23)) ? 1u : 0u;
    }
    c1 = __reduce_add_sync(FULLMASK, c1);
    c2 = __reduce_add_sync(FULLMASK, c2);
    if (lane == 0) { sm.wsum[wid] = c1; sm.wsum2[wid] = c2; }
    __syncthreads();
    unsigned tc1 = 0, tc2 = 0;
#pragma unroll
    for (int w = 0; w < NWARP; w++) { tc1 += sm.wsum[w]; tc2 += sm.wsum2[w]; }
    __syncthreads();

    unsigned pv, r;
    if (tc2 < (unsigned)KSEL && (unsigned)KSEL <= tc1) {
        // k-th |x| lies in [1,2): exponent byte is 127. (Holds with >30 sigma
        // margin for N(0,1) rows; exact check keeps it correct regardless.)
        pv = 127u;
        r  = (unsigned)KSEL - tc2;
    } else {
        pv = 0u; r = (unsigned)KSEL;
        run_level(&sm, key, 31u, 23u, 0xFFu, 256, tid, lane, wid, pv, r); // exponent
    }
    run_level(&sm, key, 23u, 15u, 0xFFu, 256, tid, lane, wid, pv, r); // mantissa[22:15]
    run_level(&sm, key, 15u,  7u, 0xFFu, 256, tid, lane, wid, pv, r); // mantissa[14:7]
    run_level(&sm, key,  7u,  0u, 0x7Fu, 128, tid, lane, wid, pv, r); // mantissa[6:0]
    const unsigned T = pv;  // exact 31-bit key of the 409th-largest |x|

    // ---- Exact tie handling: keep only the first r equal-to-T elements
    //      in linear-index order (matches lax.top_k stability). ----
    if (tid == 0) sm.eqcnt = 0;
    __syncthreads();
#pragma unroll
    for (int e = 0; e < NELEM; e++) {
        if (key[e] == T) {
            unsigned p = atomicAdd(&sm.eqcnt, 1u);
            if (p < 64u)
                sm.eqidx[p] = (((unsigned)tid + (unsigned)(e >> 2) * NTHREAD) << 2) + (unsigned)(e & 3);
        }
    }
    __syncthreads();
    unsigned ce = sm.eqcnt;
    if (ce > 64u) ce = 0u;  // pathological overflow: keep all ties

    // ---- Masked write-back ----
#pragma unroll
    for (int j = 0; j < NVEC; j++) {
        uint4 o;
        unsigned comp[4];
#pragma unroll
        for (int c = 0; c < 4; c++) {
            const int e = 4*j + c;
            const unsigned k = key[e];
            bool keep = (k > T);
            if (k == T) {
                unsigned myidx = (((unsigned)tid + (unsigned)j * NTHREAD) << 2) + (unsigned)c;
                unsigned rank = 0;
                for (unsigned i = 0; i < ce; i++)
                    rank += (sm.eqidx[i] < myidx) ? 1u : 0u;
                keep = (rank < r);
            }
            comp[c] = keep ? (k | (((signs >> e) & 1u) << 31)) : 0u;
        }
        o.x = comp[0]; o.y = comp[1]; o.z = comp[2]; o.w = comp[3];
        yout[tid + j * NTHREAD] = o;
    }
}

extern "C" void kernel_launch(void* const* d_in, const int* in_sizes, int n_in,
                              void* d_out, int out_size) {
    const float* x = (const float*)d_in[0];
    float* y = (float*)d_out;
    const int nrows = in_sizes[0] / HW;   // 16384 for 64*256 rows
    topk_sparse_kernel<<<nrows, NTHREAD>>>(x, y);
}

// round 3
// speedup vs baseline: 2.5720x; 2.5720x over previous
#include <cuda_runtime.h>
#include <cstdint>
#include <cstddef>

#define FULLMASK 0xFFFFFFFFu

namespace {
constexpr int      HW      = 4096;   // 64*64
constexpr unsigned KSEL    = 409;    // int(0.1 * 4096)
constexpr int      NTHREAD = 256;
constexpr int      NWARP   = 8;
constexpr int      CAP     = 64;     // candidate capacity for selected bin
}

struct SmemT {
    unsigned hist[256];
    unsigned wsum[NWARP];
    unsigned cnt;
    unsigned sel;       // selected bin (0xFFFFFFFF = none)
    unsigned r2;        // rank within selected bin
    unsigned Ts;        // threshold in s-domain (|x| bits << 1)
    unsigned inv_star;  // inverted-index cutoff for exact ties
    unsigned cs[CAP];
    unsigned cinv[CAP];
};

// bin = trunc(|x|*800 - 1200): bin 0 <=> |x| < 1.50125 (6.2 sigma below the
// 409th-order-statistic for N(0,1) rows), bin >= 255 <=> |x| >= 1.81875
// (7.6 sigma above). Monotone in |x|; identical expression used in both the
// histogram and retrieval passes, so bin equality is exact.
__device__ __forceinline__ int bin_of(unsigned u) {
    float ax = fabsf(__uint_as_float(u));
    return (int)fmaf(ax, 800.0f, -1200.0f);
}

// Block-wide total of per-thread count c (broadcast to all threads).
// Only used on the (almost never taken) exact fallback path.
__device__ __forceinline__ unsigned blk_total(SmemT* sm, unsigned c, int lane, int wid) {
    c = __reduce_add_sync(FULLMASK, c);
    __syncthreads();               // protect wsum reuse across calls
    if (lane == 0) sm->wsum[wid] = c;
    __syncthreads();
    unsigned t = 0;
#pragma unroll
    for (int w = 0; w < NWARP; w++) t += sm->wsum[w];
    return t;
}

__global__ void __launch_bounds__(NTHREAD, 5)
topk_sparse_kernel(const float* __restrict__ x, float* __restrict__ y)
{
    __shared__ SmemT sm;
    const int tid  = threadIdx.x;
    const int lane = tid & 31;
    const int wid  = tid >> 5;
    const size_t rowbase = (size_t)blockIdx.x * (HW / 4);
    const uint4* xin  = reinterpret_cast<const uint4*>(x) + rowbase;
    uint4*       yout = reinterpret_cast<uint4*>(y) + rowbase;

    // ---- load row: 16 elements/thread, original bits kept (sign intact) ----
    unsigned u[16];
#pragma unroll
    for (int j = 0; j < 4; j++) {
        uint4 t = xin[tid + j * NTHREAD];
        u[4*j+0] = t.x; u[4*j+1] = t.y; u[4*j+2] = t.z; u[4*j+3] = t.w;
    }
    // element e lives at linear index 4*tid + 1024*(e>>2) + (e&3); inv = 4095 - idx
    const unsigned invbase = 4095u - ((unsigned)tid << 2);

    sm.hist[tid] = 0;
    if (tid == 0) { sm.cnt = 0; sm.sel = 0xFFFFFFFFu; }
    __syncthreads();

    // ---- single histogram pass: only ~546/4096 elements participate ----
#pragma unroll
    for (int e = 0; e < 16; e++) {
        int bin = min(bin_of(u[e]), 255);
        if (bin >= 1) atomicAdd(&sm.hist[bin], 1u);
    }
    __syncthreads();

    // ---- descending cumulative scan: find bin containing rank KSEL ----
    {
        int b = 255 - tid;
        unsigned cb = (b >= 1) ? sm.hist[b] : 0u;   // bin 0 uncounted by design
        unsigned incl = cb;
#pragma unroll
        for (int d = 1; d < 32; d <<= 1) {
            unsigned n = __shfl_up_sync(FULLMASK, incl, d);
            if (lane >= d) incl += n;
        }
        if (lane == 31) sm.wsum[wid] = incl;
        __syncthreads();
#pragma unroll
        for (int w = 0; w < NWARP - 1; w++)
            if (w < wid) incl += sm.wsum[w];
        unsigned excl = incl - cb;
        if (excl < KSEL && KSEL <= incl) { sm.sel = (unsigned)b; sm.r2 = KSEL - excl; }
    }
    __syncthreads();

    // ---- retrieve the (expected ~1) candidates of the selected bin ----
    const unsigned sel = sm.sel;
#pragma unroll
    for (int e = 0; e < 16; e++) {
        if (bin_of(u[e]) == (int)sel) {
            unsigned pos = atomicAdd(&sm.cnt, 1u);
            if (pos < (unsigned)CAP) {
                sm.cs[pos]   = u[e] << 1;   // 31-bit |x| key, order-preserving
                sm.cinv[pos] = invbase - (unsigned)((e >> 2) * 1024 + (e & 3));
            }
        }
    }
    __syncthreads();

    const bool fb = (sel == 0xFFFFFFFFu) || (sel >= 255u) || (sm.cnt > (unsigned)CAP);
    if (!fb) {
        // ---- exact selection of rank r2 within the bin (ties by index) ----
        const unsigned m2 = sm.cnt;
        const unsigned r2 = sm.r2;
        if ((unsigned)tid < m2) {
            unsigned si = sm.cs[tid], vi = sm.cinv[tid];
            unsigned rank = 0;
            for (unsigned j = 0; j < m2; j++) {
                unsigned sj = sm.cs[j], vj = sm.cinv[j];
                rank += (sj > si || (sj == si && vj > vi)) ? 1u : 0u;
            }
            if (rank == r2 - 1u) { sm.Ts = si; sm.inv_star = vi; }
        }
    } else {
        // ---- exact fallback: bitwise binary search (block-uniform) ----
        unsigned lo = 0;                       // s values are even; bit0 skipped
        for (int bit = 31; bit >= 1; bit--) {
            unsigned T = lo | (1u << bit);
            unsigned c = 0;
#pragma unroll
            for (int e = 0; e < 16; e++) c += ((u[e] << 1) >= T) ? 1u : 0u;
            if (blk_total(&sm, c, lane, wid) >= KSEL) lo = T;
        }
        const unsigned Tsf = lo;               // exact KSEL-th largest key (s-domain)
        unsigned cgt = 0;
#pragma unroll
        for (int e = 0; e < 16; e++) cgt += ((u[e] << 1) > Tsf) ? 1u : 0u;
        cgt = blk_total(&sm, cgt, lane, wid);
        const unsigned req = KSEL - cgt;       // >= 1 by construction
        unsigned vlo = 0;
        for (int bit = 11; bit >= 0; bit--) {
            unsigned V = vlo | (1u << bit);
            unsigned c = 0;
#pragma unroll
            for (int e = 0; e < 16; e++) {
                unsigned inv = invbase - (unsigned)((e >> 2) * 1024 + (e & 3));
                c += (((u[e] << 1) == Tsf) && inv >= V) ? 1u : 0u;
            }
            if (blk_total(&sm, c, lane, wid) >= req) vlo = V;
        }
        if (tid == 0) { sm.Ts = Tsf; sm.inv_star = vlo; }
    }
    __syncthreads();

    const unsigned Ts    = sm.Ts;
    const unsigned istar = sm.inv_star;

    // ---- masked write-back: keep iff strictly above threshold, or equal
    //      with index among the first (tie cutoff encoded in inv_star) ----
#pragma unroll
    for (int j = 0; j < 4; j++) {
        unsigned v[4];
#pragma unroll
        for (int c = 0; c < 4; c++) {
            const int e = 4*j + c;
            const unsigned s   = u[e] << 1;
            const unsigned inv = invbase - (unsigned)(j * 1024 + c);
            const bool keep = (s > Ts) || (s == Ts && inv >= istar);
            v[c] = keep ? u[e] : 0u;
        }
        uint4 o; o.x = v[0]; o.y = v[1]; o.z = v[2]; o.w = v[3];
        yout[tid + j * NTHREAD] = o;
    }
}

extern "C" void kernel_launch(void* const* d_in, const int* in_sizes, int n_in,
                              void* d_out, int out_size) {
    const float* x = (const float*)d_in[0];
    float* y = (float*)d_out;
    const int nrows = in_sizes[0] / HW;   // 16384 rows of 4096
    topk_sparse_kernel<<<nrows, NTHREAD>>>(x, y);
}